// round 1
// baseline (speedup 1.0000x reference)
#include <cuda_runtime.h>
#include <math.h>

// Problem constants
#define Bc   2
#define Sc   4096
#define Dc   512
#define Hc   8
#define DHc  64
#define Lc   128
#define Wwin 128
#define EXTc 64
#define WINc 256
#define Gc   32
#define HDc  512      // H*DH
#define HLc  1024     // H*L
#define MR   (Bc*Sc)  // 8192
#define NKEY 384      // L + WIN
#define NCH  16       // S-chunks for Kc/Vc partials

// ---------------- scratch (static device globals; no allocation) ----------------
__device__ float g_Q [MR*HDc];
__device__ float g_K [MR*HDc];
__device__ float g_V [MR*HDc];
__device__ float g_HS[MR*HLc];
__device__ float g_Kc[Bc*Lc*HDc];
__device__ float g_Vc[Bc*Lc*HDc];
__device__ float g_Kcp[NCH*Bc*Lc*HDc];
__device__ float g_Vcp[NCH*Bc*Lc*HDc];
__device__ float g_SC[(size_t)Bc*Hc*Sc*NKEY];
__device__ float g_C [MR*HDc];
__device__ float g_pm[NCH*Bc*HLc];
__device__ float g_pl[NCH*Bc*HLc];
__device__ float g_Mx[Bc*HLc];
__device__ float g_Ls[Bc*HLc];

// ---------------- 128x128x8 register-tiled SGEMM with bias (+ optional scale) ----
__global__ __launch_bounds__(256) void sgemm_bias(
    const float* __restrict__ A, const float* __restrict__ Bw,
    const float* __restrict__ bias, float* __restrict__ C,
    int Mn, int Nn, int Kn, float scale)
{
    __shared__ float As[8][128];
    __shared__ float Bs[8][128];
    int tid = threadIdx.x;
    int bm = blockIdx.y * 128, bn = blockIdx.x * 128;
    int tx = tid & 15, ty = tid >> 4;
    int ar = tid >> 1, ac = (tid & 1) * 4;
    int br = tid >> 5, bc = (tid & 31) * 4;
    float acc[8][8];
    #pragma unroll
    for (int i = 0; i < 8; i++)
        #pragma unroll
        for (int j = 0; j < 8; j++) acc[i][j] = 0.f;

    for (int kt = 0; kt < Kn; kt += 8) {
        float4 a4 = *(const float4*)(A + (size_t)(bm + ar) * Kn + kt + ac);
        As[ac + 0][ar] = a4.x; As[ac + 1][ar] = a4.y;
        As[ac + 2][ar] = a4.z; As[ac + 3][ar] = a4.w;
        float4 b4 = *(const float4*)(Bw + (size_t)(kt + br) * Nn + bn + bc);
        *(float4*)&Bs[br][bc] = b4;
        __syncthreads();
        #pragma unroll
        for (int k = 0; k < 8; k++) {
            float a[8], b[8];
            *(float4*)&a[0] = *(float4*)&As[k][ty * 8];
            *(float4*)&a[4] = *(float4*)&As[k][ty * 8 + 4];
            *(float4*)&b[0] = *(float4*)&Bs[k][tx * 8];
            *(float4*)&b[4] = *(float4*)&Bs[k][tx * 8 + 4];
            #pragma unroll
            for (int i = 0; i < 8; i++)
                #pragma unroll
                for (int j = 0; j < 8; j++)
                    acc[i][j] += a[i] * b[j];
        }
        __syncthreads();
    }
    #pragma unroll
    for (int i = 0; i < 8; i++) {
        int row = bm + ty * 8 + i;
        #pragma unroll
        for (int j = 0; j < 8; j += 4) {
            int col = bn + tx * 8 + j;
            float4 o;
            o.x = (acc[i][j + 0] + bias[col + 0]) * scale;
            o.y = (acc[i][j + 1] + bias[col + 1]) * scale;
            o.z = (acc[i][j + 2] + bias[col + 2]) * scale;
            o.w = (acc[i][j + 3] + bias[col + 3]) * scale;
            *(float4*)(C + (size_t)row * Nn + col) = o;
        }
    }
}

// ---------------- row LayerNorm over 512 (in place), 128 threads/row ----------------
__global__ __launch_bounds__(128) void ln_rows(
    float* __restrict__ X, const float* __restrict__ gg, const float* __restrict__ bb)
{
    int row = blockIdx.x;
    float* x = X + (size_t)row * 512;
    int tid = threadIdx.x;
    int lane = tid & 31, wid = tid >> 5;
    float4 v = *(float4*)&x[tid * 4];
    float s = v.x + v.y + v.z + v.w;
    #pragma unroll
    for (int o = 16; o > 0; o >>= 1) s += __shfl_xor_sync(0xffffffffu, s, o);
    __shared__ float red[4], red2[4];
    if (lane == 0) red[wid] = s;
    __syncthreads();
    float mean = (red[0] + red[1] + red[2] + red[3]) * (1.0f / 512.0f);
    float dx = v.x - mean, dy = v.y - mean, dz = v.z - mean, dw = v.w - mean;
    float ss = dx * dx + dy * dy + dz * dz + dw * dw;
    #pragma unroll
    for (int o = 16; o > 0; o >>= 1) ss += __shfl_xor_sync(0xffffffffu, ss, o);
    if (lane == 0) red2[wid] = ss;
    __syncthreads();
    float rstd = rsqrtf((red2[0] + red2[1] + red2[2] + red2[3]) * (1.0f / 512.0f) + 1e-5f);
    float4 g4 = *(const float4*)&gg[tid * 4];
    float4 b4 = *(const float4*)&bb[tid * 4];
    float4 o;
    o.x = dx * rstd * g4.x + b4.x;
    o.y = dy * rstd * g4.y + b4.y;
    o.z = dz * rstd * g4.z + b4.z;
    o.w = dw * rstd * g4.w + b4.w;
    *(float4*)&x[tid * 4] = o;
}

// ---------------- column softmax (over S) on [B,S,1024] : 3 stages ----------------
__global__ __launch_bounds__(256) void colsm_partial(
    const float* __restrict__ HS, float* __restrict__ pm, float* __restrict__ pl)
{
    int col = blockIdx.x * 256 + threadIdx.x;   // 0..2047
    int chunk = blockIdx.y;                     // 0..15
    int b = col >> 10;
    int c = col & 1023;
    const float* base = HS + (size_t)b * Sc * HLc + c;
    int s0 = chunk * (Sc / NCH);                // 256 rows
    float m = -1e30f;
    for (int r = 0; r < Sc / NCH; r++) m = fmaxf(m, base[(size_t)(s0 + r) * HLc]);
    float l = 0.f;
    for (int r = 0; r < Sc / NCH; r++) l += __expf(base[(size_t)(s0 + r) * HLc] - m);
    pm[chunk * (Bc * HLc) + col] = m;
    pl[chunk * (Bc * HLc) + col] = l;
}

__global__ __launch_bounds__(256) void colsm_combine(
    const float* __restrict__ pm, const float* __restrict__ pl,
    float* __restrict__ Mx, float* __restrict__ Ls)
{
    int col = blockIdx.x * 256 + threadIdx.x;
    float m = -1e30f;
    #pragma unroll
    for (int c = 0; c < NCH; c++) m = fmaxf(m, pm[c * (Bc * HLc) + col]);
    float l = 0.f;
    #pragma unroll
    for (int c = 0; c < NCH; c++)
        l += pl[c * (Bc * HLc) + col] * __expf(pm[c * (Bc * HLc) + col] - m);
    Mx[col] = m;
    Ls[col] = l;
}

__global__ __launch_bounds__(256) void colsm_final(
    float* __restrict__ HS, const float* __restrict__ Mx, const float* __restrict__ Ls)
{
    int i = blockIdx.x * 256 + threadIdx.x;   // 0..8388607
    int b = i >> 22;                          // / (S*HL)
    int c = i & 1023;
    int col = b * HLc + c;
    HS[i] = __expf(HS[i] - Mx[col]) / Ls[col];
}

// ---------------- Kc/Vc = hs^T @ K / V, split over 16 S-chunks (deterministic) ------
__global__ __launch_bounds__(256) void kcvc_kernel(
    const float* __restrict__ HS, const float* __restrict__ K, const float* __restrict__ V,
    float* __restrict__ pk, float* __restrict__ pv)
{
    int b = blockIdx.z, h = blockIdx.y, sc = blockIdx.x; // sc 0..15
    __shared__ float Hs[32][128];
    __shared__ float Ks[32][64];
    __shared__ float Vs[32][64];
    int tid = threadIdx.x;
    int lidx = tid >> 3;       // 0..31 -> l block of 4
    int didx = tid & 7;        // 0..7  -> d block of 8
    int l0 = lidx * 4, d0 = didx * 8;
    float ck[4][8], cv[4][8];
    #pragma unroll
    for (int i = 0; i < 4; i++)
        #pragma unroll
        for (int j = 0; j < 8; j++) { ck[i][j] = 0.f; cv[i][j] = 0.f; }

    for (int it = 0; it < 8; it++) {
        int s0 = sc * (Sc / NCH) + it * 32;
        for (int i = tid; i < 32 * 128; i += 256) {
            int s = i >> 7, l = i & 127;
            Hs[s][l] = HS[(size_t)(b * Sc + s0 + s) * HLc + h * Lc + l];
        }
        for (int i = tid; i < 32 * 64; i += 256) {
            int s = i >> 6, d = i & 63;
            size_t off = (size_t)(b * Sc + s0 + s) * HDc + h * DHc + d;
            Ks[s][d] = K[off];
            Vs[s][d] = V[off];
        }
        __syncthreads();
        #pragma unroll 4
        for (int s = 0; s < 32; s++) {
            float hl[4], kd[8], vd[8];
            #pragma unroll
            for (int i = 0; i < 4; i++) hl[i] = Hs[s][l0 + i];
            *(float4*)&kd[0] = *(float4*)&Ks[s][d0];
            *(float4*)&kd[4] = *(float4*)&Ks[s][d0 + 4];
            *(float4*)&vd[0] = *(float4*)&Vs[s][d0];
            *(float4*)&vd[4] = *(float4*)&Vs[s][d0 + 4];
            #pragma unroll
            for (int i = 0; i < 4; i++)
                #pragma unroll
                for (int j = 0; j < 8; j++) {
                    ck[i][j] += hl[i] * kd[j];
                    cv[i][j] += hl[i] * vd[j];
                }
        }
        __syncthreads();
    }
    size_t base = (size_t)sc * (Bc * Lc * HDc);
    #pragma unroll
    for (int i = 0; i < 4; i++)
        #pragma unroll
        for (int j = 0; j < 8; j++) {
            size_t idx = (size_t)(b * Lc + l0 + i) * HDc + h * DHc + d0 + j;
            pk[base + idx] = ck[i][j];
            pv[base + idx] = cv[i][j];
        }
}

__global__ __launch_bounds__(256) void reduce_partials(
    const float* __restrict__ pk, const float* __restrict__ pv,
    float* __restrict__ Kc, float* __restrict__ Vc)
{
    int i = blockIdx.x * 256 + threadIdx.x;  // 0..131071
    float a = 0.f, v = 0.f;
    #pragma unroll
    for (int c = 0; c < NCH; c++) {
        a += pk[(size_t)c * (Bc * Lc * HDc) + i];
        v += pv[(size_t)c * (Bc * Lc * HDc) + i];
    }
    Kc[i] = a;
    Vc[i] = v;
}

// ---------------- scores: per (b,h,g) compute 128 q x 384 keys -> global ------------
__global__ __launch_bounds__(256) void scores_kernel(
    const float* __restrict__ Q, const float* __restrict__ K,
    const float* __restrict__ KcL, const int* __restrict__ mask,
    float* __restrict__ SC)
{
    int g = blockIdx.x, h = blockIdx.y, b = blockIdx.z;
    __shared__ float Keys[128][68];   // pad 68 to avoid bank conflicts
    int tid = threadIdx.x;
    int q = tid >> 1, half = tid & 1;
    int qs = g * Wwin + q;
    float4 Qr[16];
    const float* qrow = Q + (size_t)(b * Sc + qs) * HDc + h * DHc;
    #pragma unroll
    for (int i = 0; i < 16; i++) Qr[i] = *(const float4*)(qrow + i * 4);
    float* out = SC + (size_t)((b * Hc + h) * Sc + qs) * NKEY;

    for (int ch = 0; ch < 3; ch++) {
        for (int i = tid; i < 128 * 64; i += 256) {
            int k = i >> 6, d = i & 63;
            float val;
            if (ch == 0) {
                val = KcL[(size_t)(b * Lc + k) * HDc + h * DHc + d];
            } else {
                int sp = g * Wwin + (ch - 1) * 128 + k - EXTc;
                val = (sp >= 0 && sp < Sc) ? K[(size_t)(b * Sc + sp) * HDc + h * DHc + d] : 0.f;
            }
            Keys[k][d] = val;
        }
        __syncthreads();
        for (int j = 0; j < 64; j++) {
            int k = j * 2 + half;
            float s = 0.f;
            #pragma unroll
            for (int dc = 0; dc < 16; dc++) {
                float4 k4 = *(float4*)&Keys[k][dc * 4];
                s += Qr[dc].x * k4.x + Qr[dc].y * k4.y + Qr[dc].z * k4.z + Qr[dc].w * k4.w;
            }
            if (ch > 0) {
                int sp = g * Wwin + (ch - 1) * 128 + k - EXTc;
                if (sp < 0 || sp >= Sc || mask[b * Sc + sp] == 0) s = -1e30f;
            }
            out[ch * 128 + k] = s;
        }
        __syncthreads();
    }
}

// ---------------- row softmax over 384 + query-pad zeroing (warp per row) -----------
__global__ __launch_bounds__(256) void softmax_rows(
    float* __restrict__ SC, const int* __restrict__ mask)
{
    int row = blockIdx.x * 8 + (threadIdx.x >> 5);   // 0..65535
    int lane = threadIdx.x & 31;
    int b = row >> 15;          // / (H*S)
    int q = row & (Sc - 1);
    float* p = SC + (size_t)row * NKEY;
    float v[12];
    float m = -1e30f;
    #pragma unroll
    for (int i = 0; i < 12; i++) { v[i] = p[lane + i * 32]; m = fmaxf(m, v[i]); }
    #pragma unroll
    for (int o = 16; o > 0; o >>= 1) m = fmaxf(m, __shfl_xor_sync(0xffffffffu, m, o));
    float l = 0.f;
    #pragma unroll
    for (int i = 0; i < 12; i++) { v[i] = __expf(v[i] - m); l += v[i]; }
    #pragma unroll
    for (int o = 16; o > 0; o >>= 1) l += __shfl_xor_sync(0xffffffffu, l, o);
    float inv = 1.f / l;
    if (mask[b * Sc + q] == 0) inv = 0.f;
    #pragma unroll
    for (int i = 0; i < 12; i++) p[lane + i * 32] = v[i] * inv;
}

// ---------------- attention output: C = P[:, :384] @ [Vc ; V_window] ----------------
__global__ __launch_bounds__(256) void attn_out(
    const float* __restrict__ SC, const float* __restrict__ VcL,
    const float* __restrict__ V, float* __restrict__ C)
{
    int g = blockIdx.x, h = blockIdx.y, b = blockIdx.z;
    __shared__ float Vs[128][64];
    int tid = threadIdx.x;
    int q = tid >> 1, half = tid & 1, d0 = half * 32;
    int qs = g * Wwin + q;
    const float* prow = SC + (size_t)((b * Hc + h) * Sc + qs) * NKEY;
    float acc[32];
    #pragma unroll
    for (int j = 0; j < 32; j++) acc[j] = 0.f;

    for (int ch = 0; ch < 3; ch++) {
        for (int i = tid; i < 128 * 64; i += 256) {
            int k = i >> 6, d = i & 63;
            float val;
            if (ch == 0) {
                val = VcL[(size_t)(b * Lc + k) * HDc + h * DHc + d];
            } else {
                int sp = g * Wwin + (ch - 1) * 128 + k - EXTc;
                val = (sp >= 0 && sp < Sc) ? V[(size_t)(b * Sc + sp) * HDc + h * DHc + d] : 0.f;
            }
            Vs[k][d] = val;
        }
        __syncthreads();
        #pragma unroll 2
        for (int k = 0; k < 128; k++) {
            float pv = prow[ch * 128 + k];
            #pragma unroll
            for (int jc = 0; jc < 8; jc++) {
                float4 v4 = *(float4*)&Vs[k][d0 + jc * 4];
                acc[jc * 4 + 0] += pv * v4.x;
                acc[jc * 4 + 1] += pv * v4.y;
                acc[jc * 4 + 2] += pv * v4.z;
                acc[jc * 4 + 3] += pv * v4.w;
            }
        }
        __syncthreads();
    }
    float* crow = C + (size_t)(b * Sc + qs) * HDc + h * DHc + d0;
    #pragma unroll
    for (int jc = 0; jc < 8; jc++) {
        float4 o;
        o.x = acc[jc * 4 + 0]; o.y = acc[jc * 4 + 1];
        o.z = acc[jc * 4 + 2]; o.w = acc[jc * 4 + 3];
        *(float4*)(crow + jc * 4) = o;
    }
}

// ---------------- host launch ----------------
extern "C" void kernel_launch(void* const* d_in, const int* in_sizes, int n_in,
                              void* d_out, int out_size)
{
    const float* X    = (const float*)d_in[0];
    const int*   mask = (const int*)  d_in[1];
    const float* Wq   = (const float*)d_in[2];
    const float* bq   = (const float*)d_in[3];
    const float* Wk   = (const float*)d_in[4];
    const float* bk   = (const float*)d_in[5];
    const float* Wv   = (const float*)d_in[6];
    const float* bv   = (const float*)d_in[7];
    const float* Wo   = (const float*)d_in[8];
    const float* bo   = (const float*)d_in[9];
    const float* lng  = (const float*)d_in[10];
    const float* lnb  = (const float*)d_in[11];
    const float* lsg  = (const float*)d_in[12];
    const float* lsb  = (const float*)d_in[13];
    const float* Wd   = (const float*)d_in[14];
    const float* bd   = (const float*)d_in[15];
    float* out = (float*)d_out;

    float *Qp, *Kp, *Vp, *HSp, *Kcp, *Vcp, *Kpp, *Vpp, *SCp, *Cp, *pmp, *plp, *Mxp, *Lsp;
    cudaGetSymbolAddress((void**)&Qp,  g_Q);
    cudaGetSymbolAddress((void**)&Kp,  g_K);
    cudaGetSymbolAddress((void**)&Vp,  g_V);
    cudaGetSymbolAddress((void**)&HSp, g_HS);
    cudaGetSymbolAddress((void**)&Kcp, g_Kc);
    cudaGetSymbolAddress((void**)&Vcp, g_Vc);
    cudaGetSymbolAddress((void**)&Kpp, g_Kcp);
    cudaGetSymbolAddress((void**)&Vpp, g_Vcp);
    cudaGetSymbolAddress((void**)&SCp, g_SC);
    cudaGetSymbolAddress((void**)&Cp,  g_C);
    cudaGetSymbolAddress((void**)&pmp, g_pm);
    cudaGetSymbolAddress((void**)&plp, g_pl);
    cudaGetSymbolAddress((void**)&Mxp, g_Mx);
    cudaGetSymbolAddress((void**)&Lsp, g_Ls);

    dim3 gQKV(HDc / 128, MR / 128);   // (4, 64)
    dim3 gWd(HLc / 128, MR / 128);    // (8, 64)

    sgemm_bias<<<gQKV, 256>>>(X, Wq, bq, Qp, MR, HDc, Dc, 0.125f);
    sgemm_bias<<<gQKV, 256>>>(X, Wk, bk, Kp, MR, HDc, Dc, 1.f);
    sgemm_bias<<<gQKV, 256>>>(X, Wv, bv, Vp, MR, HDc, Dc, 1.f);
    ln_rows<<<MR, 128>>>(Kp, lng, lnb);
    ln_rows<<<MR, 128>>>(Vp, lng, lnb);

    sgemm_bias<<<gWd, 256>>>(X, Wd, bd, HSp, MR, HLc, Dc, 1.f);
    colsm_partial<<<dim3(8, NCH), 256>>>(HSp, pmp, plp);
    colsm_combine<<<8, 256>>>(pmp, plp, Mxp, Lsp);
    colsm_final<<<(MR * HLc) / 256, 256>>>(HSp, Mxp, Lsp);

    kcvc_kernel<<<dim3(NCH, Hc, Bc), 256>>>(HSp, Kp, Vp, Kpp, Vpp);
    reduce_partials<<<(Bc * Lc * HDc) / 256, 256>>>(Kpp, Vpp, Kcp, Vcp);
    ln_rows<<<Bc * Lc, 128>>>(Kcp, lsg, lsb);
    ln_rows<<<Bc * Lc, 128>>>(Vcp, lsg, lsb);

    scores_kernel<<<dim3(Gc, Hc, Bc), 256>>>(Qp, Kp, Kcp, mask, SCp);
    softmax_rows<<<(Bc * Hc * Sc) / 8, 256>>>(SCp, mask);
    attn_out<<<dim3(Gc, Hc, Bc), 256>>>(SCp, Vcp, Vp, Cp);

    sgemm_bias<<<gQKV, 256>>>(Cp, Wo, bo, out, MR, HDc, Dc, 1.f);
}

// round 4
// speedup vs baseline: 1.4356x; 1.4356x over previous
#include <cuda_runtime.h>
#include <cuda_bf16.h>
#include <cstdint>
#include <math.h>

// Problem constants
#define Bc   2
#define Sc   4096
#define Dc   512
#define Hc   8
#define DHc  64
#define Lc   128
#define Wwin 128
#define EXTc 64
#define WINc 256
#define Gc   32
#define HDc  512      // H*DH
#define HLc  1024     // H*L
#define MR   (Bc*Sc)  // 8192
#define NKEY 384      // L + WIN
#define NCH  16       // S-chunks for Kc/Vc partials

// ---------------- scratch (static device globals; no allocation) ----------------
__device__ float g_Q [MR*HDc];
__device__ float g_K [MR*HDc];
__device__ float g_V [MR*HDc];
__device__ float g_HS[MR*HLc];
__device__ float g_Kc[Bc*Lc*HDc];
__device__ float g_Vc[Bc*Lc*HDc];
__device__ float g_Kcp[NCH*Bc*Lc*HDc];
__device__ float g_Vcp[NCH*Bc*Lc*HDc];
__device__ float g_SC[(size_t)Bc*Hc*Sc*NKEY];
__device__ float g_C [MR*HDc];
__device__ float g_pm[NCH*Bc*HLc];
__device__ float g_pl[NCH*Bc*HLc];
__device__ float g_Mx[Bc*HLc];
__device__ float g_Ls[Bc*HLc];
// bf16 split operands (16B-aligned for uint4 loads)
__device__ __align__(16) __nv_bfloat16 g_Xh[MR*Dc],  g_Xl[MR*Dc];
__device__ __align__(16) __nv_bfloat16 g_Ch[MR*HDc], g_Cl[MR*HDc];
__device__ __align__(16) __nv_bfloat16 g_Wqh[HDc*Dc], g_Wql[HDc*Dc];
__device__ __align__(16) __nv_bfloat16 g_Wkh[HDc*Dc], g_Wkl[HDc*Dc];
__device__ __align__(16) __nv_bfloat16 g_Wvh[HDc*Dc], g_Wvl[HDc*Dc];
__device__ __align__(16) __nv_bfloat16 g_Woh[Dc*HDc], g_Wol[Dc*HDc];
__device__ __align__(16) __nv_bfloat16 g_Wdh[HLc*Dc], g_Wdl[HLc*Dc];

// ---------------- mma.sync wrapper (bf16 -> fp32), m16n8k16 ----------------
__device__ __forceinline__ void mma16816(
    float& c0, float& c1, float& c2, float& c3,
    uint32_t a0, uint32_t a1, uint32_t a2, uint32_t a3,
    uint32_t b0, uint32_t b1)
{
    asm volatile(
        "mma.sync.aligned.m16n8k16.row.col.f32.bf16.bf16.f32 "
        "{%0,%1,%2,%3}, {%4,%5,%6,%7}, {%8,%9}, {%0,%1,%2,%3};"
        : "+f"(c0), "+f"(c1), "+f"(c2), "+f"(c3)
        : "r"(a0), "r"(a1), "r"(a2), "r"(a3), "r"(b0), "r"(b1));
}

// ================= conversion kernels =================
__global__ __launch_bounds__(256) void cvt_split(
    const float* __restrict__ x, __nv_bfloat16* __restrict__ hi,
    __nv_bfloat16* __restrict__ lo, int n)
{
    int i = (blockIdx.x * 256 + threadIdx.x) * 4;
    if (i >= n) return;
    float4 v = *(const float4*)(x + i);
    float a[4] = {v.x, v.y, v.z, v.w};
    __nv_bfloat16 h[4], l[4];
    #pragma unroll
    for (int j = 0; j < 4; j++) {
        h[j] = __float2bfloat16(a[j]);
        l[j] = __float2bfloat16(a[j] - __bfloat162float(h[j]));
    }
    *(uint2*)(hi + i) = *(uint2*)h;
    *(uint2*)(lo + i) = *(uint2*)l;
}

// W [K=512, N] row-major -> T [N, 512] K-major, split hi/lo
__global__ __launch_bounds__(256) void transpose_cvt(
    const float* __restrict__ W, __nv_bfloat16* __restrict__ Th,
    __nv_bfloat16* __restrict__ Tl, int Nn)
{
    __shared__ float t[32][33];
    int n0 = blockIdx.x * 32, k0 = blockIdx.y * 32;
    int tx = threadIdx.x & 31, ty = threadIdx.x >> 5;  // 32 x 8
    #pragma unroll
    for (int i = 0; i < 32; i += 8)
        t[ty + i][tx] = W[(size_t)(k0 + ty + i) * Nn + n0 + tx];
    __syncthreads();
    #pragma unroll
    for (int i = 0; i < 32; i += 8) {
        float v = t[tx][ty + i];   // = W[k0+tx][n0+ty+i]
        __nv_bfloat16 h = __float2bfloat16(v);
        __nv_bfloat16 l = __float2bfloat16(v - __bfloat162float(h));
        size_t o = (size_t)(n0 + ty + i) * 512 + k0 + tx;
        Th[o] = h; Tl[o] = l;
    }
}

// ============ HMMA split-bf16 GEMM: C[M,Nn] = A[M,512] @ T[Nn,512]^T + bias ==========
// CTA tile 128x128, BK=32 bf16. 8 warps: warp_m in {0,1} (64 rows), warp_n in {0..3} (32 cols).
// Warp tile 64x32: 4 m16 x 4 n8 mma tiles.
#define KSTRIDE 20   // u32 stride per smem row (16 payload + 4 pad)
__global__ __launch_bounds__(256) void gemm_hmma(
    const __nv_bfloat16* __restrict__ Ahi, const __nv_bfloat16* __restrict__ Alo,
    const __nv_bfloat16* __restrict__ Bhi, const __nv_bfloat16* __restrict__ Blo,
    const float* __restrict__ bias, float* __restrict__ C, int Nn, float scale)
{
    __shared__ uint32_t AsH[128 * KSTRIDE], AsL[128 * KSTRIDE];
    __shared__ uint32_t BsH[128 * KSTRIDE], BsL[128 * KSTRIDE];
    const int tid = threadIdx.x, wid = tid >> 5, lane = tid & 31;
    const int g = lane >> 2, tig = lane & 3;
    const int warp_m = wid & 1, warp_n = wid >> 1;
    const int bm = blockIdx.y * 128, bn = blockIdx.x * 128;

    float acc[4][4][4];
    #pragma unroll
    for (int mt = 0; mt < 4; mt++)
        #pragma unroll
        for (int nt = 0; nt < 4; nt++)
            #pragma unroll
            for (int e = 0; e < 4; e++) acc[mt][nt][e] = 0.f;

    for (int kt = 0; kt < 512; kt += 32) {
        // stage 128x32 bf16 tiles (2x uint4 per thread per array)
        #pragma unroll
        for (int p = 0; p < 2; p++) {
            int i = tid + p * 256;        // 0..511
            int r = i >> 2, c = (i & 3) * 4;
            size_t goA = (size_t)(bm + r) * 512 + kt + c * 2;
            size_t goB = (size_t)(bn + r) * 512 + kt + c * 2;
            *(uint4*)&AsH[r * KSTRIDE + c] = *(const uint4*)(Ahi + goA);
            *(uint4*)&AsL[r * KSTRIDE + c] = *(const uint4*)(Alo + goA);
            *(uint4*)&BsH[r * KSTRIDE + c] = *(const uint4*)(Bhi + goB);
            *(uint4*)&BsL[r * KSTRIDE + c] = *(const uint4*)(Blo + goB);
        }
        __syncthreads();

        #pragma unroll
        for (int ks = 0; ks < 2; ks++) {
            const int kc = ks * 8 + tig;
            uint32_t aH[4][4], aL[4][4], bH[4][2], bL[4][2];
            #pragma unroll
            for (int mt = 0; mt < 4; mt++) {
                int m0 = warp_m * 64 + mt * 16;
                aH[mt][0] = AsH[(m0 + g) * KSTRIDE + kc];
                aH[mt][1] = AsH[(m0 + g + 8) * KSTRIDE + kc];
                aH[mt][2] = AsH[(m0 + g) * KSTRIDE + kc + 4];
                aH[mt][3] = AsH[(m0 + g + 8) * KSTRIDE + kc + 4];
                aL[mt][0] = AsL[(m0 + g) * KSTRIDE + kc];
                aL[mt][1] = AsL[(m0 + g + 8) * KSTRIDE + kc];
                aL[mt][2] = AsL[(m0 + g) * KSTRIDE + kc + 4];
                aL[mt][3] = AsL[(m0 + g + 8) * KSTRIDE + kc + 4];
            }
            #pragma unroll
            for (int nt = 0; nt < 4; nt++) {
                int n0 = warp_n * 32 + nt * 8;
                bH[nt][0] = BsH[(n0 + g) * KSTRIDE + kc];
                bH[nt][1] = BsH[(n0 + g) * KSTRIDE + kc + 4];
                bL[nt][0] = BsL[(n0 + g) * KSTRIDE + kc];
                bL[nt][1] = BsL[(n0 + g) * KSTRIDE + kc + 4];
            }
            #pragma unroll
            for (int mt = 0; mt < 4; mt++)
                #pragma unroll
                for (int nt = 0; nt < 4; nt++) {
                    float* c4 = acc[mt][nt];
                    mma16816(c4[0], c4[1], c4[2], c4[3],
                             aH[mt][0], aH[mt][1], aH[mt][2], aH[mt][3],
                             bH[nt][0], bH[nt][1]);
                    mma16816(c4[0], c4[1], c4[2], c4[3],
                             aH[mt][0], aH[mt][1], aH[mt][2], aH[mt][3],
                             bL[nt][0], bL[nt][1]);
                    mma16816(c4[0], c4[1], c4[2], c4[3],
                             aL[mt][0], aL[mt][1], aL[mt][2], aL[mt][3],
                             bH[nt][0], bH[nt][1]);
                }
        }
        __syncthreads();
    }

    // epilogue
    #pragma unroll
    for (int mt = 0; mt < 4; mt++) {
        int row0 = bm + warp_m * 64 + mt * 16 + g;
        #pragma unroll
        for (int nt = 0; nt < 4; nt++) {
            int col = bn + warp_n * 32 + nt * 8 + tig * 2;
            float b0 = bias[col], b1 = bias[col + 1];
            float2 o0, o1;
            o0.x = (acc[mt][nt][0] + b0) * scale;
            o0.y = (acc[mt][nt][1] + b1) * scale;
            o1.x = (acc[mt][nt][2] + b0) * scale;
            o1.y = (acc[mt][nt][3] + b1) * scale;
            *(float2*)(C + (size_t)row0 * Nn + col) = o0;
            *(float2*)(C + (size_t)(row0 + 8) * Nn + col) = o1;
        }
    }
}

// ---------------- row LayerNorm over 512 (in place), 128 threads/row ----------------
__global__ __launch_bounds__(128) void ln_rows(
    float* __restrict__ X, const float* __restrict__ gg, const float* __restrict__ bb)
{
    int row = blockIdx.x;
    float* x = X + (size_t)row * 512;
    int tid = threadIdx.x;
    int lane = tid & 31, wid = tid >> 5;
    float4 v = *(float4*)&x[tid * 4];
    float s = v.x + v.y + v.z + v.w;
    #pragma unroll
    for (int o = 16; o > 0; o >>= 1) s += __shfl_xor_sync(0xffffffffu, s, o);
    __shared__ float red[4], red2[4];
    if (lane == 0) red[wid] = s;
    __syncthreads();
    float mean = (red[0] + red[1] + red[2] + red[3]) * (1.0f / 512.0f);
    float dx = v.x - mean, dy = v.y - mean, dz = v.z - mean, dw = v.w - mean;
    float ss = dx * dx + dy * dy + dz * dz + dw * dw;
    #pragma unroll
    for (int o = 16; o > 0; o >>= 1) ss += __shfl_xor_sync(0xffffffffu, ss, o);
    if (lane == 0) red2[wid] = ss;
    __syncthreads();
    float rstd = rsqrtf((red2[0] + red2[1] + red2[2] + red2[3]) * (1.0f / 512.0f) + 1e-5f);
    float4 g4 = *(const float4*)&gg[tid * 4];
    float4 b4 = *(const float4*)&bb[tid * 4];
    float4 o;
    o.x = dx * rstd * g4.x + b4.x;
    o.y = dy * rstd * g4.y + b4.y;
    o.z = dz * rstd * g4.z + b4.z;
    o.w = dw * rstd * g4.w + b4.w;
    *(float4*)&x[tid * 4] = o;
}

// ---------------- column softmax (over S) on [B,S,1024] : 3 stages ----------------
__global__ __launch_bounds__(256) void colsm_partial(
    const float* __restrict__ HS, float* __restrict__ pm, float* __restrict__ pl)
{
    int col = blockIdx.x * 256 + threadIdx.x;
    int chunk = blockIdx.y;
    int b = col >> 10;
    int c = col & 1023;
    const float* base = HS + (size_t)b * Sc * HLc + c;
    int s0 = chunk * (Sc / NCH);
    float m = -1e30f;
    for (int r = 0; r < Sc / NCH; r++) m = fmaxf(m, base[(size_t)(s0 + r) * HLc]);
    float l = 0.f;
    for (int r = 0; r < Sc / NCH; r++) l += __expf(base[(size_t)(s0 + r) * HLc] - m);
    pm[chunk * (Bc * HLc) + col] = m;
    pl[chunk * (Bc * HLc) + col] = l;
}

__global__ __launch_bounds__(256) void colsm_combine(
    const float* __restrict__ pm, const float* __restrict__ pl,
    float* __restrict__ Mx, float* __restrict__ Ls)
{
    int col = blockIdx.x * 256 + threadIdx.x;
    float m = -1e30f;
    #pragma unroll
    for (int c = 0; c < NCH; c++) m = fmaxf(m, pm[c * (Bc * HLc) + col]);
    float l = 0.f;
    #pragma unroll
    for (int c = 0; c < NCH; c++)
        l += pl[c * (Bc * HLc) + col] * __expf(pm[c * (Bc * HLc) + col] - m);
    Mx[col] = m;
    Ls[col] = l;
}

__global__ __launch_bounds__(256) void colsm_final(
    float* __restrict__ HS, const float* __restrict__ Mx, const float* __restrict__ Ls)
{
    int i = blockIdx.x * 256 + threadIdx.x;
    int b = i >> 22;
    int c = i & 1023;
    int col = b * HLc + c;
    HS[i] = __expf(HS[i] - Mx[col]) / Ls[col];
}

// ---------------- Kc/Vc = hs^T @ K / V, split over 16 S-chunks (deterministic) ------
__global__ __launch_bounds__(256) void kcvc_kernel(
    const float* __restrict__ HS, const float* __restrict__ K, const float* __restrict__ V,
    float* __restrict__ pk, float* __restrict__ pv)
{
    int b = blockIdx.z, h = blockIdx.y, sc = blockIdx.x;
    __shared__ float Hs[32][128];
    __shared__ float Ks[32][64];
    __shared__ float Vs[32][64];
    int tid = threadIdx.x;
    int lidx = tid >> 3;
    int didx = tid & 7;
    int l0 = lidx * 4, d0 = didx * 8;
    float ck[4][8], cv[4][8];
    #pragma unroll
    for (int i = 0; i < 4; i++)
        #pragma unroll
        for (int j = 0; j < 8; j++) { ck[i][j] = 0.f; cv[i][j] = 0.f; }

    for (int it = 0; it < 8; it++) {
        int s0 = sc * (Sc / NCH) + it * 32;
        for (int i = tid; i < 32 * 128; i += 256) {
            int s = i >> 7, l = i & 127;
            Hs[s][l] = HS[(size_t)(b * Sc + s0 + s) * HLc + h * Lc + l];
        }
        for (int i = tid; i < 32 * 64; i += 256) {
            int s = i >> 6, d = i & 63;
            size_t off = (size_t)(b * Sc + s0 + s) * HDc + h * DHc + d;
            Ks[s][d] = K[off];
            Vs[s][d] = V[off];
        }
        __syncthreads();
        #pragma unroll 4
        for (int s = 0; s < 32; s++) {
            float hl[4], kd[8], vd[8];
            #pragma unroll
            for (int i = 0; i < 4; i++) hl[i] = Hs[s][l0 + i];
            *(float4*)&kd[0] = *(float4*)&Ks[s][d0];
            *(float4*)&kd[4] = *(float4*)&Ks[s][d0 + 4];
            *(float4*)&vd[0] = *(float4*)&Vs[s][d0];
            *(float4*)&vd[4] = *(float4*)&Vs[s][d0 + 4];
            #pragma unroll
            for (int i = 0; i < 4; i++)
                #pragma unroll
                for (int j = 0; j < 8; j++) {
                    ck[i][j] += hl[i] * kd[j];
                    cv[i][j] += hl[i] * vd[j];
                }
        }
        __syncthreads();
    }
    size_t base = (size_t)sc * (Bc * Lc * HDc);
    #pragma unroll
    for (int i = 0; i < 4; i++)
        #pragma unroll
        for (int j = 0; j < 8; j++) {
            size_t idx = (size_t)(b * Lc + l0 + i) * HDc + h * DHc + d0 + j;
            pk[base + idx] = ck[i][j];
            pv[base + idx] = cv[i][j];
        }
}

__global__ __launch_bounds__(256) void reduce_partials(
    const float* __restrict__ pk, const float* __restrict__ pv,
    float* __restrict__ Kc, float* __restrict__ Vc)
{
    int i = blockIdx.x * 256 + threadIdx.x;
    float a = 0.f, v = 0.f;
    #pragma unroll
    for (int c = 0; c < NCH; c++) {
        a += pk[(size_t)c * (Bc * Lc * HDc) + i];
        v += pv[(size_t)c * (Bc * Lc * HDc) + i];
    }
    Kc[i] = a;
    Vc[i] = v;
}

// ---------------- scores: per (b,h,g) compute 128 q x 384 keys -> global ------------
__global__ __launch_bounds__(256) void scores_kernel(
    const float* __restrict__ Q, const float* __restrict__ K,
    const float* __restrict__ KcL, const int* __restrict__ mask,
    float* __restrict__ SC)
{
    int g = blockIdx.x, h = blockIdx.y, b = blockIdx.z;
    __shared__ float Keys[128][68];
    int tid = threadIdx.x;
    int q = tid >> 1, half = tid & 1;
    int qs = g * Wwin + q;
    float4 Qr[16];
    const float* qrow = Q + (size_t)(b * Sc + qs) * HDc + h * DHc;
    #pragma unroll
    for (int i = 0; i < 16; i++) Qr[i] = *(const float4*)(qrow + i * 4);
    float* out = SC + (size_t)((b * Hc + h) * Sc + qs) * NKEY;

    for (int ch = 0; ch < 3; ch++) {
        for (int i = tid; i < 128 * 64; i += 256) {
            int k = i >> 6, d = i & 63;
            float val;
            if (ch == 0) {
                val = KcL[(size_t)(b * Lc + k) * HDc + h * DHc + d];
            } else {
                int sp = g * Wwin + (ch - 1) * 128 + k - EXTc;
                val = (sp >= 0 && sp < Sc) ? K[(size_t)(b * Sc + sp) * HDc + h * DHc + d] : 0.f;
            }
            Keys[k][d] = val;
        }
        __syncthreads();
        for (int j = 0; j < 64; j++) {
            int k = j * 2 + half;
            float s = 0.f;
            #pragma unroll
            for (int dc = 0; dc < 16; dc++) {
                float4 k4 = *(float4*)&Keys[k][dc * 4];
                s += Qr[dc].x * k4.x + Qr[dc].y * k4.y + Qr[dc].z * k4.z + Qr[dc].w * k4.w;
            }
            if (ch > 0) {
                int sp = g * Wwin + (ch - 1) * 128 + k - EXTc;
                if (sp < 0 || sp >= Sc || mask[b * Sc + sp] == 0) s = -1e30f;
            }
            out[ch * 128 + k] = s;
        }
        __syncthreads();
    }
}

// ---------------- row softmax over 384 + query-pad zeroing (warp per row) -----------
__global__ __launch_bounds__(256) void softmax_rows(
    float* __restrict__ SC, const int* __restrict__ mask)
{
    int row = blockIdx.x * 8 + (threadIdx.x >> 5);
    int lane = threadIdx.x & 31;
    int b = row >> 15;
    int q = row & (Sc - 1);
    float* p = SC + (size_t)row * NKEY;
    float v[12];
    float m = -1e30f;
    #pragma unroll
    for (int i = 0; i < 12; i++) { v[i] = p[lane + i * 32]; m = fmaxf(m, v[i]); }
    #pragma unroll
    for (int o = 16; o > 0; o >>= 1) m = fmaxf(m, __shfl_xor_sync(0xffffffffu, m, o));
    float l = 0.f;
    #pragma unroll
    for (int i = 0; i < 12; i++) { v[i] = __expf(v[i] - m); l += v[i]; }
    #pragma unroll
    for (int o = 16; o > 0; o >>= 1) l += __shfl_xor_sync(0xffffffffu, l, o);
    float inv = 1.f / l;
    if (mask[b * Sc + q] == 0) inv = 0.f;
    #pragma unroll
    for (int i = 0; i < 12; i++) p[lane + i * 32] = v[i] * inv;
}

// ---------------- attention output: C = P[:, :384] @ [Vc ; V_window] ----------------
__global__ __launch_bounds__(256) void attn_out(
    const float* __restrict__ SC, const float* __restrict__ VcL,
    const float* __restrict__ V, float* __restrict__ C)
{
    int g = blockIdx.x, h = blockIdx.y, b = blockIdx.z;
    __shared__ float Vs[128][64];
    int tid = threadIdx.x;
    int q = tid >> 1, half = tid & 1, d0 = half * 32;
    int qs = g * Wwin + q;
    const float* prow = SC + (size_t)((b * Hc + h) * Sc + qs) * NKEY;
    float acc[32];
    #pragma unroll
    for (int j = 0; j < 32; j++) acc[j] = 0.f;

    for (int ch = 0; ch < 3; ch++) {
        for (int i = tid; i < 128 * 64; i += 256) {
            int k = i >> 6, d = i & 63;
            float val;
            if (ch == 0) {
                val = VcL[(size_t)(b * Lc + k) * HDc + h * DHc + d];
            } else {
                int sp = g * Wwin + (ch - 1) * 128 + k - EXTc;
                val = (sp >= 0 && sp < Sc) ? V[(size_t)(b * Sc + sp) * HDc + h * DHc + d] : 0.f;
            }
            Vs[k][d] = val;
        }
        __syncthreads();
        #pragma unroll 2
        for (int k = 0; k < 128; k++) {
            float pv = prow[ch * 128 + k];
            #pragma unroll
            for (int jc = 0; jc < 8; jc++) {
                float4 v4 = *(float4*)&Vs[k][d0 + jc * 4];
                acc[jc * 4 + 0] += pv * v4.x;
                acc[jc * 4 + 1] += pv * v4.y;
                acc[jc * 4 + 2] += pv * v4.z;
                acc[jc * 4 + 3] += pv * v4.w;
            }
        }
        __syncthreads();
    }
    float* crow = C + (size_t)(b * Sc + qs) * HDc + h * DHc + d0;
    #pragma unroll
    for (int jc = 0; jc < 8; jc++) {
        float4 o;
        o.x = acc[jc * 4 + 0]; o.y = acc[jc * 4 + 1];
        o.z = acc[jc * 4 + 2]; o.w = acc[jc * 4 + 3];
        *(float4*)(crow + jc * 4) = o;
    }
}

// ---------------- host launch ----------------
extern "C" void kernel_launch(void* const* d_in, const int* in_sizes, int n_in,
                              void* d_out, int out_size)
{
    const float* X    = (const float*)d_in[0];
    const int*   mask = (const int*)  d_in[1];
    const float* Wq   = (const float*)d_in[2];
    const float* bq   = (const float*)d_in[3];
    const float* Wk   = (const float*)d_in[4];
    const float* bk   = (const float*)d_in[5];
    const float* Wv   = (const float*)d_in[6];
    const float* bv   = (const float*)d_in[7];
    const float* Wo   = (const float*)d_in[8];
    const float* bo   = (const float*)d_in[9];
    const float* lng  = (const float*)d_in[10];
    const float* lnb  = (const float*)d_in[11];
    const float* lsg  = (const float*)d_in[12];
    const float* lsb  = (const float*)d_in[13];
    const float* Wd   = (const float*)d_in[14];
    const float* bd   = (const float*)d_in[15];
    float* out = (float*)d_out;

    float *Qp, *Kp, *Vp, *HSp, *Kcp, *Vcp, *Kpp, *Vpp, *SCp, *Cp, *pmp, *plp, *Mxp, *Lsp;
    cudaGetSymbolAddress((void**)&Qp,  g_Q);
    cudaGetSymbolAddress((void**)&Kp,  g_K);
    cudaGetSymbolAddress((void**)&Vp,  g_V);
    cudaGetSymbolAddress((void**)&HSp, g_HS);
    cudaGetSymbolAddress((void**)&Kcp, g_Kc);
    cudaGetSymbolAddress((void**)&Vcp, g_Vc);
    cudaGetSymbolAddress((void**)&Kpp, g_Kcp);
    cudaGetSymbolAddress((void**)&Vpp, g_Vcp);
    cudaGetSymbolAddress((void**)&SCp, g_SC);
    cudaGetSymbolAddress((void**)&Cp,  g_C);
    cudaGetSymbolAddress((void**)&pmp, g_pm);
    cudaGetSymbolAddress((void**)&plp, g_pl);
    cudaGetSymbolAddress((void**)&Mxp, g_Mx);
    cudaGetSymbolAddress((void**)&Lsp, g_Ls);

    __nv_bfloat16 *Xh, *Xl, *Ch, *Cl, *Wqh, *Wql, *Wkh, *Wkl, *Wvh, *Wvl, *Woh, *Wol, *Wdh, *Wdl;
    cudaGetSymbolAddress((void**)&Xh,  g_Xh);  cudaGetSymbolAddress((void**)&Xl,  g_Xl);
    cudaGetSymbolAddress((void**)&Ch,  g_Ch);  cudaGetSymbolAddress((void**)&Cl,  g_Cl);
    cudaGetSymbolAddress((void**)&Wqh, g_Wqh); cudaGetSymbolAddress((void**)&Wql, g_Wql);
    cudaGetSymbolAddress((void**)&Wkh, g_Wkh); cudaGetSymbolAddress((void**)&Wkl, g_Wkl);
    cudaGetSymbolAddress((void**)&Wvh, g_Wvh); cudaGetSymbolAddress((void**)&Wvl, g_Wvl);
    cudaGetSymbolAddress((void**)&Woh, g_Woh); cudaGetSymbolAddress((void**)&Wol, g_Wol);
    cudaGetSymbolAddress((void**)&Wdh, g_Wdh); cudaGetSymbolAddress((void**)&Wdl, g_Wdl);

    // operand conversion
    cvt_split<<<(MR * Dc) / 1024, 256>>>(X, Xh, Xl, MR * Dc);
    transpose_cvt<<<dim3(HDc / 32, Dc / 32), 256>>>(Wq, Wqh, Wql, HDc);
    transpose_cvt<<<dim3(HDc / 32, Dc / 32), 256>>>(Wk, Wkh, Wkl, HDc);
    transpose_cvt<<<dim3(HDc / 32, Dc / 32), 256>>>(Wv, Wvh, Wvl, HDc);
    transpose_cvt<<<dim3(HLc / 32, Dc / 32), 256>>>(Wd, Wdh, Wdl, HLc);
    transpose_cvt<<<dim3(Dc / 32, HDc / 32), 256>>>(Wo, Woh, Wol, Dc);

    // projections (HMMA tensor cores)
    gemm_hmma<<<dim3(4, 64), 256>>>(Xh, Xl, Wqh, Wql, bq, Qp, HDc, 0.125f);
    gemm_hmma<<<dim3(4, 64), 256>>>(Xh, Xl, Wkh, Wkl, bk, Kp, HDc, 1.f);
    gemm_hmma<<<dim3(4, 64), 256>>>(Xh, Xl, Wvh, Wvl, bv, Vp, HDc, 1.f);
    gemm_hmma<<<dim3(8, 64), 256>>>(Xh, Xl, Wdh, Wdl, bd, HSp, HLc, 1.f);

    ln_rows<<<MR, 128>>>(Kp, lng, lnb);
    ln_rows<<<MR, 128>>>(Vp, lng, lnb);

    colsm_partial<<<dim3(8, NCH), 256>>>(HSp, pmp, plp);
    colsm_combine<<<8, 256>>>(pmp, plp, Mxp, Lsp);
    colsm_final<<<(MR * HLc) / 256, 256>>>(HSp, Mxp, Lsp);

    kcvc_kernel<<<dim3(NCH, Hc, Bc), 256>>>(HSp, Kp, Vp, Kpp, Vpp);
    reduce_partials<<<(Bc * Lc * HDc) / 256, 256>>>(Kpp, Vpp, Kcp, Vcp);
    ln_rows<<<Bc * Lc, 128>>>(Kcp, lsg, lsb);
    ln_rows<<<Bc * Lc, 128>>>(Vcp, lsg, lsb);

    scores_kernel<<<dim3(Gc, Hc, Bc), 256>>>(Qp, Kp, Kcp, mask, SCp);
    softmax_rows<<<(Bc * Hc * Sc) / 8, 256>>>(SCp, mask);
    attn_out<<<dim3(Gc, Hc, Bc), 256>>>(SCp, Vcp, Vp, Cp);

    // output projection (HMMA tensor cores)
    cvt_split<<<(MR * HDc) / 1024, 256>>>(Cp, Ch, Cl, MR * HDc);
    gemm_hmma<<<dim3(4, 64), 256>>>(Ch, Cl, Woh, Wol, bo, out, HDc, 1.f);
}